// round 11
// baseline (speedup 1.0000x reference)
#include <cuda_runtime.h>
#include <cuda_bf16.h>

#define N_NODES 50000
#define N_EDGES 800000
#define C_IN   512
#define C_H1   512
#define C_OUT  256

typedef __nv_bfloat16 bf16;

// ---------------- device scratch (no allocations allowed) ----------------
__device__ __align__(16) float g_T[(size_t)N_NODES * C_H1];   // GEMM output
__device__ __align__(16) float g_H[(size_t)N_NODES * C_H1];   // hidden (fp32, for residual)
__device__ __align__(16) bf16  g_Hh[(size_t)N_NODES * C_H1];  // hidden hi (GEMM A)
__device__ __align__(16) bf16  g_Hl[(size_t)N_NODES * C_H1];  // hidden lo
__device__ __align__(16) bf16  g_W1h[C_IN * C_H1],  g_W1l[C_IN * C_H1];   // [N][K] transposed
__device__ __align__(16) bf16  g_Wrh[C_H1 * C_H1],  g_Wrl[C_H1 * C_H1];
__device__ __align__(16) bf16  g_Wxh[C_H1 * C_OUT], g_Wxl[C_H1 * C_OUT];
__device__ float g_dinv[N_NODES];
__device__ int   g_cnt[N_NODES];
__device__ int   g_cnt2[N_NODES];
__device__ int   g_rowptr[N_NODES + 1];
__device__ int   g_colsrc[N_EDGES];
__device__ float g_norm[N_EDGES];
__device__ int   g_is64;

__device__ __forceinline__ int edge_at(const void* ei, long long idx) {
    if (g_is64) return (int)((const long long*)ei)[idx];
    return ((const int*)ei)[idx];
}

__device__ __forceinline__ void split_bf16(float v, bf16& hi, bf16& lo) {
    hi = __float2bfloat16(v);
    lo = __float2bfloat16(v - __bfloat162float(hi));
}

// ---------------- dtype sniffer (parallel) ----------------
__global__ void k_detect(const void* ei) {
    const int* w = (const int*)ei;
    __shared__ unsigned s[256];
    unsigned acc = 0;
    for (int i = threadIdx.x; i < 2048; i += 256) acc |= (unsigned)w[2 * i + 1];
    s[threadIdx.x] = acc;
    __syncthreads();
    for (int off = 128; off > 0; off >>= 1) {
        if (threadIdx.x < off) s[threadIdx.x] |= s[threadIdx.x + off];
        __syncthreads();
    }
    if (threadIdx.x == 0) g_is64 = (s[0] == 0) ? 1 : 0;
}

// ---------------- graph prep ----------------
__global__ void k_zero_counts() {
    int i = blockIdx.x * blockDim.x + threadIdx.x;
    if (i < N_NODES) { g_cnt[i] = 0; g_cnt2[i] = 0; }
}

__global__ void k_count(const void* __restrict__ ei) {
    int e = blockIdx.x * blockDim.x + threadIdx.x;
    if (e < N_EDGES) {
        int d = edge_at(ei, (long long)N_EDGES + e);
        if (d >= 0 && d < N_NODES) atomicAdd(&g_cnt[d], 1);
    }
}

__global__ void k_dinv() {
    int i = blockIdx.x * blockDim.x + threadIdx.x;
    if (i < N_NODES) g_dinv[i] = rsqrtf((float)g_cnt[i] + 1.0f);
}

__global__ void k_scan() {
    const int T = 1024;
    int tid = threadIdx.x;
    const int chunk = (N_NODES + T - 1) / T;
    int beg = tid * chunk;
    int end = min(beg + chunk, N_NODES);
    int sum = 0;
    for (int i = beg; i < end; i++) sum += g_cnt[i];
    __shared__ int s[T];
    s[tid] = sum;
    __syncthreads();
    for (int off = 1; off < T; off <<= 1) {
        int v = (tid >= off) ? s[tid - off] : 0;
        __syncthreads();
        s[tid] += v;
        __syncthreads();
    }
    int run = (tid > 0) ? s[tid - 1] : 0;
    for (int i = beg; i < end; i++) { g_rowptr[i] = run; run += g_cnt[i]; }
    if (tid == T - 1) g_rowptr[N_NODES] = N_EDGES;
}

__global__ void k_scatter(const void* __restrict__ ei) {
    int e = blockIdx.x * blockDim.x + threadIdx.x;
    if (e < N_EDGES) {
        int s = edge_at(ei, e);
        int d = edge_at(ei, (long long)N_EDGES + e);
        if (s < 0 || s >= N_NODES || d < 0 || d >= N_NODES) return;
        int pos = g_rowptr[d] + atomicAdd(&g_cnt2[d], 1);
        if (pos >= 0 && pos < N_EDGES) {
            g_colsrc[pos] = s;
            g_norm[pos] = g_dinv[s] * g_dinv[d];
        }
    }
}

// ---------------- operand pre-split ----------------
__global__ void k_split_x(const float* __restrict__ x) {
    size_t i = (size_t)blockIdx.x * blockDim.x + threadIdx.x;
    const size_t total4 = (size_t)N_NODES * C_IN / 4;
    if (i >= total4) return;
    float4 v = ((const float4*)x)[i];
    bf16 h[4], l[4];
    split_bf16(v.x, h[0], l[0]); split_bf16(v.y, h[1], l[1]);
    split_bf16(v.z, h[2], l[2]); split_bf16(v.w, h[3], l[3]);
    ((__nv_bfloat162*)g_Hh)[2 * i]     = __nv_bfloat162(h[0], h[1]);
    ((__nv_bfloat162*)g_Hh)[2 * i + 1] = __nv_bfloat162(h[2], h[3]);
    ((__nv_bfloat162*)g_Hl)[2 * i]     = __nv_bfloat162(l[0], l[1]);
    ((__nv_bfloat162*)g_Hl)[2 * i + 1] = __nv_bfloat162(l[2], l[3]);
}

// W[K][N] fp32 -> Wt_h/Wt_l [N][K] bf16 (transposed)
__global__ void k_split_w(const float* __restrict__ W, int K, int N, int sel) {
    bf16 *Wh, *Wl;
    if (sel == 0)      { Wh = g_W1h; Wl = g_W1l; }
    else if (sel == 1) { Wh = g_Wrh; Wl = g_Wrl; }
    else               { Wh = g_Wxh; Wl = g_Wxl; }
    int idx = blockIdx.x * blockDim.x + threadIdx.x;
    if (idx >= K * N) return;
    int n = idx / K, k = idx % K;
    bf16 h, l;
    split_bf16(W[(size_t)k * N + n], h, l);
    Wh[(size_t)n * K + k] = h;
    Wl[(size_t)n * K + k] = l;
}

// ---------------- tensor-core GEMM ----------------
// CTA tile 128x128, 4 warps in 2x2, each 64x64. BK=32, ldmatrix fragments,
// cp.async double buffer. bf16x3: acc += ah*bh + ah*bl + al*bh.
#define BM 128
#define BN 128
#define BK 32
#define AST (BK + 8)    // 40 bf16 row stride = 80B; bank(row r)=20r mod 32: conflict-free

__device__ __forceinline__ void mma_bf16(float* c, const unsigned* a, const unsigned* b) {
    asm volatile(
        "mma.sync.aligned.m16n8k16.row.col.f32.bf16.bf16.f32 "
        "{%0,%1,%2,%3}, {%4,%5,%6,%7}, {%8,%9}, {%0,%1,%2,%3};"
        : "+f"(c[0]), "+f"(c[1]), "+f"(c[2]), "+f"(c[3])
        : "r"(a[0]), "r"(a[1]), "r"(a[2]), "r"(a[3]), "r"(b[0]), "r"(b[1]));
}

__device__ __forceinline__ void ldsm4(unsigned* r, unsigned addr) {
    asm volatile("ldmatrix.sync.aligned.m8n8.x4.shared.b16 {%0,%1,%2,%3}, [%4];"
                 : "=r"(r[0]), "=r"(r[1]), "=r"(r[2]), "=r"(r[3]) : "r"(addr));
}

__device__ __forceinline__ void cp16(void* dst, const void* src, bool valid) {
    unsigned d = (unsigned)__cvta_generic_to_shared(dst);
    int sz = valid ? 16 : 0;
    asm volatile("cp.async.ca.shared.global [%0], [%1], 16, %2;\n"
                 :: "r"(d), "l"(src), "r"(sz));
}
__device__ __forceinline__ void cp_commit() { asm volatile("cp.async.commit_group;"); }
template <int NG>
__device__ __forceinline__ void cp_wait() { asm volatile("cp.async.wait_group %0;" :: "n"(NG)); }

__global__ void __launch_bounds__(128)
k_gemm_bf16(int wsel, int M, int N, int K) {
    const bf16* Ah = g_Hh;
    const bf16* Al = g_Hl;
    const bf16 *Bh, *Bl;
    if (wsel == 0)      { Bh = g_W1h; Bl = g_W1l; }
    else if (wsel == 1) { Bh = g_Wrh; Bl = g_Wrl; }
    else                { Bh = g_Wxh; Bl = g_Wxl; }
    float* C = g_T;

    extern __shared__ char smem[];
    bf16* sAh = (bf16*)smem;                 // [2][BM][AST]
    bf16* sAl = sAh + 2 * BM * AST;
    bf16* sBh = sAl + 2 * BM * AST;          // [2][BN][AST]
    bf16* sBl = sBh + 2 * BN * AST;

    int tid  = threadIdx.x;
    int w    = tid >> 5;
    int lane = tid & 31;

    int row0 = blockIdx.y * BM;
    int col0 = blockIdx.x * BN;
    int mrow = (w & 1) * 64;     // warp M offset within CTA
    int ncol = (w >> 1) * 64;    // warp N offset within CTA

    // ldmatrix per-lane offsets (element units)
    int a_r = (lane & 7) + ((lane >> 3) & 1) * 8;   // + mrow + mg*16
    int a_c = (lane >> 4) * 8;                       // + ks
    int b_r = (lane & 7) + (lane >> 4) * 8;          // + ncol + 16*p
    int b_c = ((lane >> 3) & 1) * 8;                 // + ks

    unsigned uAh = (unsigned)__cvta_generic_to_shared(sAh);
    unsigned uAl = (unsigned)__cvta_generic_to_shared(sAl);
    unsigned uBh = (unsigned)__cvta_generic_to_shared(sBh);
    unsigned uBl = (unsigned)__cvta_generic_to_shared(sBl);

    float acc[4][8][4];          // [mg][n8][frag]
#pragma unroll
    for (int mg = 0; mg < 4; mg++)
#pragma unroll
        for (int n = 0; n < 8; n++)
#pragma unroll
            for (int j = 0; j < 4; j++) acc[mg][n][j] = 0.0f;

    auto prefetch = [&](int st, int kt) {
        // A: 128 rows x 4 chunks (16B) x {h,l} -> 1024 cp / 128 thr = 8 (4 iters x2)
#pragma unroll
        for (int it = 0; it < 4; it++) {
            int idx = tid + it * 128;
            int r = idx >> 2, c16 = idx & 3;
            bool v = (row0 + r) < M;
            size_t goff = (size_t)(row0 + r) * K + kt + c16 * 8;
            int soff = st * BM * AST + r * AST + c16 * 8;
            cp16(&sAh[soff], Ah + goff, v);
            cp16(&sAl[soff], Al + goff, v);
        }
        // B: 128 rows x 4 chunks x {h,l}
#pragma unroll
        for (int it = 0; it < 4; it++) {
            int idx = tid + it * 128;
            int r = idx >> 2, c16 = idx & 3;
            size_t goff = (size_t)(col0 + r) * K + kt + c16 * 8;
            int soff = st * BN * AST + r * AST + c16 * 8;
            cp16(&sBh[soff], Bh + goff, true);
            cp16(&sBl[soff], Bl + goff, true);
        }
    };

    const int nk = K / BK;
    prefetch(0, 0);
    cp_commit();

    for (int ik = 0; ik < nk; ik++) {
        int cur = ik & 1;
        if (ik + 1 < nk) {
            prefetch(cur ^ 1, (ik + 1) * BK);
            cp_commit();
            cp_wait<1>();
        } else {
            cp_wait<0>();
        }
        __syncthreads();

        int aBase = cur * BM * AST;
        int bBase = cur * BN * AST;

#pragma unroll
        for (int ks = 0; ks < BK; ks += 16) {
            unsigned ah[4][4], al[4][4];
#pragma unroll
            for (int mg = 0; mg < 4; mg++) {
                int off = aBase + (mrow + mg * 16 + a_r) * AST + ks + a_c;
                ldsm4(ah[mg], uAh + off * 2);
                ldsm4(al[mg], uAl + off * 2);
            }
#pragma unroll
            for (int p = 0; p < 4; p++) {
                unsigned bh[4], bl[4];
                int off = bBase + (ncol + 16 * p + b_r) * AST + ks + b_c;
                ldsm4(bh, uBh + off * 2);
                ldsm4(bl, uBl + off * 2);
#pragma unroll
                for (int mg = 0; mg < 4; mg++) {
                    mma_bf16(acc[mg][2 * p],     ah[mg], bh);
                    mma_bf16(acc[mg][2 * p],     ah[mg], bl);
                    mma_bf16(acc[mg][2 * p],     al[mg], bh);
                    mma_bf16(acc[mg][2 * p + 1], ah[mg], bh + 2);
                    mma_bf16(acc[mg][2 * p + 1], ah[mg], bl + 2);
                    mma_bf16(acc[mg][2 * p + 1], al[mg], bh + 2);
                }
            }
        }
        __syncthreads();
    }

    // epilogue
#pragma unroll
    for (int mg = 0; mg < 4; mg++) {
        int r0 = row0 + mrow + mg * 16 + (lane >> 2);
#pragma unroll
        for (int n = 0; n < 8; n++) {
            int col = col0 + ncol + n * 8 + 2 * (lane & 3);
            if (r0 < M)
                *(float2*)&C[(size_t)r0 * N + col] = make_float2(acc[mg][n][0], acc[mg][n][1]);
            if (r0 + 8 < M)
                *(float2*)&C[(size_t)(r0 + 8) * N + col] = make_float2(acc[mg][n][2], acc[mg][n][3]);
        }
    }
}

// ---------------- CSR SpMM with fused epilogue (+ bf16 split of H) ----------------
template <int C, bool RELU, bool RES, bool TO_OUT>
__global__ void k_spmm(const float* __restrict__ bias, float* __restrict__ out) {
    constexpr int V4 = C / 4;
    int i = blockIdx.x;
    int tid = threadIdx.x;
    const float4* T4 = (const float4*)g_T;

    float di = g_dinv[i];
    float wself = di * di;
    float4 tv = T4[(size_t)i * V4 + tid];
    float4 acc = make_float4(tv.x * wself, tv.y * wself, tv.z * wself, tv.w * wself);

    int e = g_rowptr[i];
    int end = g_rowptr[i + 1];
    for (; e + 4 <= end; e += 4) {
        int   s0 = g_colsrc[e],     s1 = g_colsrc[e + 1];
        int   s2 = g_colsrc[e + 2], s3 = g_colsrc[e + 3];
        float w0 = g_norm[e],       w1 = g_norm[e + 1];
        float w2 = g_norm[e + 2],   w3 = g_norm[e + 3];
        float4 v0 = T4[(size_t)s0 * V4 + tid];
        float4 v1 = T4[(size_t)s1 * V4 + tid];
        float4 v2 = T4[(size_t)s2 * V4 + tid];
        float4 v3 = T4[(size_t)s3 * V4 + tid];
        acc.x += w0 * v0.x + w1 * v1.x + w2 * v2.x + w3 * v3.x;
        acc.y += w0 * v0.y + w1 * v1.y + w2 * v2.y + w3 * v3.y;
        acc.z += w0 * v0.z + w1 * v1.z + w2 * v2.z + w3 * v3.z;
        acc.w += w0 * v0.w + w1 * v1.w + w2 * v2.w + w3 * v3.w;
    }
    for (; e < end; e++) {
        int s = g_colsrc[e];
        float wgt = g_norm[e];
        float4 v = T4[(size_t)s * V4 + tid];
        acc.x += wgt * v.x; acc.y += wgt * v.y; acc.z += wgt * v.z; acc.w += wgt * v.w;
    }

    float4 b = ((const float4*)bias)[tid];
    acc.x += b.x; acc.y += b.y; acc.z += b.z; acc.w += b.w;

    if (RELU) {
        acc.x = fmaxf(acc.x, 0.f); acc.y = fmaxf(acc.y, 0.f);
        acc.z = fmaxf(acc.z, 0.f); acc.w = fmaxf(acc.w, 0.f);
    }
    if (RES) {
        float4 h = ((const float4*)g_H)[(size_t)i * V4 + tid];
        acc.x += h.x; acc.y += h.y; acc.z += h.z; acc.w += h.w;
    }

    if (TO_OUT) {
        ((float4*)out)[(size_t)i * V4 + tid] = acc;
    } else {
        size_t o4 = (size_t)i * V4 + tid;
        ((float4*)g_H)[o4] = acc;
        bf16 h[4], l[4];
        split_bf16(acc.x, h[0], l[0]); split_bf16(acc.y, h[1], l[1]);
        split_bf16(acc.z, h[2], l[2]); split_bf16(acc.w, h[3], l[3]);
        ((__nv_bfloat162*)g_Hh)[2 * o4]     = __nv_bfloat162(h[0], h[1]);
        ((__nv_bfloat162*)g_Hh)[2 * o4 + 1] = __nv_bfloat162(h[2], h[3]);
        ((__nv_bfloat162*)g_Hl)[2 * o4]     = __nv_bfloat162(l[0], l[1]);
        ((__nv_bfloat162*)g_Hl)[2 * o4 + 1] = __nv_bfloat162(l[2], l[3]);
    }
}

// ---------------- launch ----------------
extern "C" void kernel_launch(void* const* d_in, const int* in_sizes, int n_in,
                              void* d_out, int out_size) {
    const float* x  = (const float*)d_in[0];
    const void*  ei = d_in[1];
    const float* W1 = (const float*)d_in[2];
    const float* b1 = (const float*)d_in[3];
    const float* Wr = (const float*)d_in[4];
    const float* br = (const float*)d_in[5];
    const float* Wx = (const float*)d_in[6];
    const float* bx = (const float*)d_in[7];
    float* out      = (float*)d_out;

    const int GSMEM = 2 * (2 * BM * AST + 2 * BN * AST) * (int)sizeof(bf16);  // 81920
    cudaFuncSetAttribute(k_gemm_bf16, cudaFuncAttributeMaxDynamicSharedMemorySize, GSMEM);

    // graph prep
    k_detect<<<1, 256>>>(ei);
    k_zero_counts<<<(N_NODES + 255) / 256, 256>>>();
    k_count<<<(N_EDGES + 255) / 256, 256>>>(ei);
    k_dinv<<<(N_NODES + 255) / 256, 256>>>();
    k_scan<<<1, 1024>>>();
    k_scatter<<<(N_EDGES + 255) / 256, 256>>>(ei);

    // operand pre-split
    k_split_w<<<(C_IN * C_H1 + 255) / 256, 256>>>(W1, C_IN, C_H1, 0);
    k_split_w<<<(C_H1 * C_H1 + 255) / 256, 256>>>(Wr, C_H1, C_H1, 1);
    k_split_w<<<(C_H1 * C_OUT + 255) / 256, 256>>>(Wx, C_H1, C_OUT, 2);
    k_split_x<<<((N_NODES * C_IN / 4) + 255) / 256, 256>>>(x);

    dim3 g512(C_H1 / BN, (N_NODES + BM - 1) / BM);
    dim3 g256(C_OUT / BN, (N_NODES + BM - 1) / BM);

    // layer 0: H = relu(agg(x @ W1) + b1)
    k_gemm_bf16<<<g512, 128, GSMEM>>>(0, N_NODES, C_H1, C_IN);
    k_spmm<C_H1, true, false, false><<<N_NODES, C_H1 / 4>>>(b1, out);

    // 4 residual layers
    for (int l = 0; l < 4; l++) {
        k_gemm_bf16<<<g512, 128, GSMEM>>>(1, N_NODES, C_H1, C_H1);
        k_spmm<C_H1, true, true, false><<<N_NODES, C_H1 / 4>>>(br, out);
    }

    // final: out = agg(H @ Wx) + bx
    k_gemm_bf16<<<g256, 128, GSMEM>>>(2, N_NODES, C_OUT, C_H1);
    k_spmm<C_OUT, false, false, true><<<N_NODES, C_OUT / 4>>>(bx, out);
}

// round 12
// speedup vs baseline: 1.0937x; 1.0937x over previous
#include <cuda_runtime.h>
#include <cuda_bf16.h>

#define N_NODES 50000
#define N_EDGES 800000
#define C_IN   512
#define C_H1   512
#define C_OUT  256

typedef __nv_bfloat16 bf16;

// ---------------- device scratch (no allocations allowed) ----------------
__device__ __align__(16) float g_T[(size_t)N_NODES * C_H1];   // GEMM output
__device__ __align__(16) bf16  g_Hh[(size_t)N_NODES * C_H1];  // hidden hi (GEMM A)
__device__ __align__(16) bf16  g_Hl[(size_t)N_NODES * C_H1];  // hidden lo
__device__ __align__(16) bf16  g_W1h[C_IN * C_H1],  g_W1l[C_IN * C_H1];   // [N][K] transposed
__device__ __align__(16) bf16  g_Wrh[C_H1 * C_H1],  g_Wrl[C_H1 * C_H1];
__device__ __align__(16) bf16  g_Wxh[C_H1 * C_OUT], g_Wxl[C_H1 * C_OUT];
__device__ float g_dinv[N_NODES];
__device__ int   g_cnt[N_NODES];
__device__ int   g_cnt2[N_NODES];
__device__ int   g_rowptr[N_NODES + 1];
__device__ int   g_colsrc[N_EDGES];
__device__ float g_norm[N_EDGES];
__device__ int   g_is64;

__device__ __forceinline__ int edge_at(const void* ei, long long idx) {
    if (g_is64) return (int)((const long long*)ei)[idx];
    return ((const int*)ei)[idx];
}

__device__ __forceinline__ void split_bf16(float v, bf16& hi, bf16& lo) {
    hi = __float2bfloat16(v);
    lo = __float2bfloat16(v - __bfloat162float(hi));
}

// ---------------- dtype sniffer (parallel) ----------------
__global__ void k_detect(const void* ei) {
    const int* w = (const int*)ei;
    __shared__ unsigned s[256];
    unsigned acc = 0;
    for (int i = threadIdx.x; i < 2048; i += 256) acc |= (unsigned)w[2 * i + 1];
    s[threadIdx.x] = acc;
    __syncthreads();
    for (int off = 128; off > 0; off >>= 1) {
        if (threadIdx.x < off) s[threadIdx.x] |= s[threadIdx.x + off];
        __syncthreads();
    }
    if (threadIdx.x == 0) g_is64 = (s[0] == 0) ? 1 : 0;
}

// ---------------- graph prep ----------------
__global__ void k_zero_counts() {
    int i = blockIdx.x * blockDim.x + threadIdx.x;
    if (i < N_NODES) { g_cnt[i] = 0; g_cnt2[i] = 0; }
}

__global__ void k_count(const void* __restrict__ ei) {
    int e = blockIdx.x * blockDim.x + threadIdx.x;
    if (e < N_EDGES) {
        int d = edge_at(ei, (long long)N_EDGES + e);
        if (d >= 0 && d < N_NODES) atomicAdd(&g_cnt[d], 1);
    }
}

__global__ void k_dinv() {
    int i = blockIdx.x * blockDim.x + threadIdx.x;
    if (i < N_NODES) g_dinv[i] = rsqrtf((float)g_cnt[i] + 1.0f);
}

__global__ void k_scan() {
    const int T = 1024;
    int tid = threadIdx.x;
    const int chunk = (N_NODES + T - 1) / T;
    int beg = tid * chunk;
    int end = min(beg + chunk, N_NODES);
    int sum = 0;
    for (int i = beg; i < end; i++) sum += g_cnt[i];
    __shared__ int s[T];
    s[tid] = sum;
    __syncthreads();
    for (int off = 1; off < T; off <<= 1) {
        int v = (tid >= off) ? s[tid - off] : 0;
        __syncthreads();
        s[tid] += v;
        __syncthreads();
    }
    int run = (tid > 0) ? s[tid - 1] : 0;
    for (int i = beg; i < end; i++) { g_rowptr[i] = run; run += g_cnt[i]; }
    if (tid == T - 1) g_rowptr[N_NODES] = N_EDGES;
}

__global__ void k_scatter(const void* __restrict__ ei) {
    int e = blockIdx.x * blockDim.x + threadIdx.x;
    if (e < N_EDGES) {
        int s = edge_at(ei, e);
        int d = edge_at(ei, (long long)N_EDGES + e);
        if (s < 0 || s >= N_NODES || d < 0 || d >= N_NODES) return;
        int pos = g_rowptr[d] + atomicAdd(&g_cnt2[d], 1);
        if (pos >= 0 && pos < N_EDGES) {
            g_colsrc[pos] = s;
            g_norm[pos] = g_dinv[s] * g_dinv[d];
        }
    }
}

// ---------------- operand pre-split ----------------
__global__ void k_split_x(const float* __restrict__ x) {
    size_t i = (size_t)blockIdx.x * blockDim.x + threadIdx.x;
    const size_t total4 = (size_t)N_NODES * C_IN / 4;
    if (i >= total4) return;
    float4 v = ((const float4*)x)[i];
    bf16 h[4], l[4];
    split_bf16(v.x, h[0], l[0]); split_bf16(v.y, h[1], l[1]);
    split_bf16(v.z, h[2], l[2]); split_bf16(v.w, h[3], l[3]);
    ((__nv_bfloat162*)g_Hh)[2 * i]     = __nv_bfloat162(h[0], h[1]);
    ((__nv_bfloat162*)g_Hh)[2 * i + 1] = __nv_bfloat162(h[2], h[3]);
    ((__nv_bfloat162*)g_Hl)[2 * i]     = __nv_bfloat162(l[0], l[1]);
    ((__nv_bfloat162*)g_Hl)[2 * i + 1] = __nv_bfloat162(l[2], l[3]);
}

// W[K][N] fp32 -> Wt_h/Wt_l [N][K] bf16 (transposed)
__global__ void k_split_w(const float* __restrict__ W, int K, int N, int sel) {
    bf16 *Wh, *Wl;
    if (sel == 0)      { Wh = g_W1h; Wl = g_W1l; }
    else if (sel == 1) { Wh = g_Wrh; Wl = g_Wrl; }
    else               { Wh = g_Wxh; Wl = g_Wxl; }
    int idx = blockIdx.x * blockDim.x + threadIdx.x;
    if (idx >= K * N) return;
    int n = idx / K, k = idx % K;
    bf16 h, l;
    split_bf16(W[(size_t)k * N + n], h, l);
    Wh[(size_t)n * K + k] = h;
    Wl[(size_t)n * K + k] = l;
}

// ---------------- tensor-core GEMM (R10 config) ----------------
// 4 warps x (32x64), BM=128 BN=64 BK=32, ldmatrix, cp.async double buffer.
#define BM 128
#define BN 64
#define BK 32
#define AST (BK + 8)    // 40 bf16 row stride = 80B; conflict-free

__device__ __forceinline__ void mma_bf16(float* c, const unsigned* a, const unsigned* b) {
    asm volatile(
        "mma.sync.aligned.m16n8k16.row.col.f32.bf16.bf16.f32 "
        "{%0,%1,%2,%3}, {%4,%5,%6,%7}, {%8,%9}, {%0,%1,%2,%3};"
        : "+f"(c[0]), "+f"(c[1]), "+f"(c[2]), "+f"(c[3])
        : "r"(a[0]), "r"(a[1]), "r"(a[2]), "r"(a[3]), "r"(b[0]), "r"(b[1]));
}

__device__ __forceinline__ void ldsm4(unsigned* r, unsigned addr) {
    asm volatile("ldmatrix.sync.aligned.m8n8.x4.shared.b16 {%0,%1,%2,%3}, [%4];"
                 : "=r"(r[0]), "=r"(r[1]), "=r"(r[2]), "=r"(r[3]) : "r"(addr));
}

__device__ __forceinline__ void cp16(void* dst, const void* src, bool valid) {
    unsigned d = (unsigned)__cvta_generic_to_shared(dst);
    int sz = valid ? 16 : 0;
    asm volatile("cp.async.ca.shared.global [%0], [%1], 16, %2;\n"
                 :: "r"(d), "l"(src), "r"(sz));
}
__device__ __forceinline__ void cp_commit() { asm volatile("cp.async.commit_group;"); }
template <int NG>
__device__ __forceinline__ void cp_wait() { asm volatile("cp.async.wait_group %0;" :: "n"(NG)); }

__global__ void __launch_bounds__(128)
k_gemm_bf16(int wsel, int M, int N, int K) {
    const bf16* Ah = g_Hh;
    const bf16* Al = g_Hl;
    const bf16 *Bh, *Bl;
    if (wsel == 0)      { Bh = g_W1h; Bl = g_W1l; }
    else if (wsel == 1) { Bh = g_Wrh; Bl = g_Wrl; }
    else                { Bh = g_Wxh; Bl = g_Wxl; }
    float* C = g_T;

    extern __shared__ char smem[];
    bf16* sAh = (bf16*)smem;                 // [2][BM][AST]
    bf16* sAl = sAh + 2 * BM * AST;
    bf16* sBh = sAl + 2 * BM * AST;          // [2][BN][AST]
    bf16* sBl = sBh + 2 * BN * AST;

    int tid  = threadIdx.x;
    int w    = tid >> 5;
    int lane = tid & 31;

    int row0 = blockIdx.y * BM;
    int col0 = blockIdx.x * BN;
    int wrow = w * 32;

    int a_r = (lane & 7) + ((lane >> 3) & 1) * 8;
    int a_c = (lane >> 4) * 8;
    int b_r = (lane & 7) + (lane >> 4) * 8;
    int b_c = ((lane >> 3) & 1) * 8;

    unsigned uAh = (unsigned)__cvta_generic_to_shared(sAh);
    unsigned uAl = (unsigned)__cvta_generic_to_shared(sAl);
    unsigned uBh = (unsigned)__cvta_generic_to_shared(sBh);
    unsigned uBl = (unsigned)__cvta_generic_to_shared(sBl);

    float acc[2][8][4];
#pragma unroll
    for (int mg = 0; mg < 2; mg++)
#pragma unroll
        for (int n = 0; n < 8; n++)
#pragma unroll
            for (int j = 0; j < 4; j++) acc[mg][n][j] = 0.0f;

    auto prefetch = [&](int st, int kt) {
#pragma unroll
        for (int it = 0; it < 4; it++) {
            int idx = tid + it * 128;
            int r = idx >> 2, c16 = idx & 3;
            bool v = (row0 + r) < M;
            size_t goff = (size_t)(row0 + r) * K + kt + c16 * 8;
            int soff = st * BM * AST + r * AST + c16 * 8;
            cp16(&sAh[soff], Ah + goff, v);
            cp16(&sAl[soff], Al + goff, v);
        }
#pragma unroll
        for (int it = 0; it < 2; it++) {
            int idx = tid + it * 128;
            int r = idx >> 2, c16 = idx & 3;
            size_t goff = (size_t)(col0 + r) * K + kt + c16 * 8;
            int soff = st * BN * AST + r * AST + c16 * 8;
            cp16(&sBh[soff], Bh + goff, true);
            cp16(&sBl[soff], Bl + goff, true);
        }
    };

    const int nk = K / BK;
    prefetch(0, 0);
    cp_commit();

    for (int ik = 0; ik < nk; ik++) {
        int cur = ik & 1;
        if (ik + 1 < nk) {
            prefetch(cur ^ 1, (ik + 1) * BK);
            cp_commit();
            cp_wait<1>();
        } else {
            cp_wait<0>();
        }
        __syncthreads();

        int aBase = cur * BM * AST;
        int bBase = cur * BN * AST;

#pragma unroll
        for (int ks = 0; ks < BK; ks += 16) {
            unsigned ah[2][4], al[2][4];
#pragma unroll
            for (int mg = 0; mg < 2; mg++) {
                int off = aBase + (wrow + mg * 16 + a_r) * AST + ks + a_c;
                ldsm4(ah[mg], uAh + off * 2);
                ldsm4(al[mg], uAl + off * 2);
            }
#pragma unroll
            for (int p = 0; p < 4; p++) {
                unsigned bh[4], bl[4];
                int off = bBase + (16 * p + b_r) * AST + ks + b_c;
                ldsm4(bh, uBh + off * 2);
                ldsm4(bl, uBl + off * 2);
#pragma unroll
                for (int mg = 0; mg < 2; mg++) {
                    mma_bf16(acc[mg][2 * p],     ah[mg], bh);
                    mma_bf16(acc[mg][2 * p],     ah[mg], bl);
                    mma_bf16(acc[mg][2 * p],     al[mg], bh);
                    mma_bf16(acc[mg][2 * p + 1], ah[mg], bh + 2);
                    mma_bf16(acc[mg][2 * p + 1], ah[mg], bl + 2);
                    mma_bf16(acc[mg][2 * p + 1], al[mg], bh + 2);
                }
            }
        }
        __syncthreads();
    }

#pragma unroll
    for (int mg = 0; mg < 2; mg++) {
        int r0 = row0 + wrow + mg * 16 + (lane >> 2);
#pragma unroll
        for (int n = 0; n < 8; n++) {
            int col = col0 + n * 8 + 2 * (lane & 3);
            if (r0 < M)
                *(float2*)&C[(size_t)r0 * N + col] = make_float2(acc[mg][n][0], acc[mg][n][1]);
            if (r0 + 8 < M)
                *(float2*)&C[(size_t)(r0 + 8) * N + col] = make_float2(acc[mg][n][2], acc[mg][n][3]);
        }
    }
}

// ---------------- channel-chunked CSR SpMM with fused epilogue ----------------
// One warp per node, 128 channels (32 float4) per chunk; 8 nodes per 256-thr block.
// Sequential chunk launches keep the 25.6MB T[:,chunk] slice L2-resident.
template <int CHT, bool RELU, bool RES, bool TO_OUT>
__global__ void __launch_bounds__(256)
k_spmm_ch(const float* __restrict__ bias, float* __restrict__ out, int chunk) {
    constexpr int V4T = CHT / 4;          // float4 per row
    int slot = threadIdx.x >> 5;
    int lane = threadIdx.x & 31;
    int i = blockIdx.x * 8 + slot;
    if (i >= N_NODES) return;
    int c4 = chunk * 32 + lane;           // float4 index within row

    const float4* T4 = (const float4*)g_T;

    float di = g_dinv[i];
    float wself = di * di;
    float4 tv = T4[(size_t)i * V4T + c4];
    float4 acc = make_float4(tv.x * wself, tv.y * wself, tv.z * wself, tv.w * wself);

    int e = g_rowptr[i];
    int end = g_rowptr[i + 1];
    for (; e + 4 <= end; e += 4) {
        int   s0 = g_colsrc[e],     s1 = g_colsrc[e + 1];
        int   s2 = g_colsrc[e + 2], s3 = g_colsrc[e + 3];
        float w0 = g_norm[e],       w1 = g_norm[e + 1];
        float w2 = g_norm[e + 2],   w3 = g_norm[e + 3];
        float4 v0 = T4[(size_t)s0 * V4T + c4];
        float4 v1 = T4[(size_t)s1 * V4T + c4];
        float4 v2 = T4[(size_t)s2 * V4T + c4];
        float4 v3 = T4[(size_t)s3 * V4T + c4];
        acc.x += w0 * v0.x + w1 * v1.x + w2 * v2.x + w3 * v3.x;
        acc.y += w0 * v0.y + w1 * v1.y + w2 * v2.y + w3 * v3.y;
        acc.z += w0 * v0.z + w1 * v1.z + w2 * v2.z + w3 * v3.z;
        acc.w += w0 * v0.w + w1 * v1.w + w2 * v2.w + w3 * v3.w;
    }
    for (; e < end; e++) {
        int s = g_colsrc[e];
        float wgt = g_norm[e];
        float4 v = T4[(size_t)s * V4T + c4];
        acc.x += wgt * v.x; acc.y += wgt * v.y; acc.z += wgt * v.z; acc.w += wgt * v.w;
    }

    float4 b = ((const float4*)bias)[c4];
    acc.x += b.x; acc.y += b.y; acc.z += b.z; acc.w += b.w;

    if (RELU) {
        acc.x = fmaxf(acc.x, 0.f); acc.y = fmaxf(acc.y, 0.f);
        acc.z = fmaxf(acc.z, 0.f); acc.w = fmaxf(acc.w, 0.f);
    }

    size_t o4 = (size_t)i * V4T + c4;     // float4 index == bf162-pair index

    if (RES) {
        // reconstruct residual h = hi + lo (error ~2^-17)
        __nv_bfloat162 h0 = ((const __nv_bfloat162*)g_Hh)[2 * o4];
        __nv_bfloat162 h1 = ((const __nv_bfloat162*)g_Hh)[2 * o4 + 1];
        __nv_bfloat162 l0 = ((const __nv_bfloat162*)g_Hl)[2 * o4];
        __nv_bfloat162 l1 = ((const __nv_bfloat162*)g_Hl)[2 * o4 + 1];
        acc.x += __bfloat162float(h0.x) + __bfloat162float(l0.x);
        acc.y += __bfloat162float(h0.y) + __bfloat162float(l0.y);
        acc.z += __bfloat162float(h1.x) + __bfloat162float(l1.x);
        acc.w += __bfloat162float(h1.y) + __bfloat162float(l1.y);
    }

    if (TO_OUT) {
        ((float4*)out)[o4] = acc;
    } else {
        bf16 h[4], l[4];
        split_bf16(acc.x, h[0], l[0]); split_bf16(acc.y, h[1], l[1]);
        split_bf16(acc.z, h[2], l[2]); split_bf16(acc.w, h[3], l[3]);
        ((__nv_bfloat162*)g_Hh)[2 * o4]     = __nv_bfloat162(h[0], h[1]);
        ((__nv_bfloat162*)g_Hh)[2 * o4 + 1] = __nv_bfloat162(h[2], h[3]);
        ((__nv_bfloat162*)g_Hl)[2 * o4]     = __nv_bfloat162(l[0], l[1]);
        ((__nv_bfloat162*)g_Hl)[2 * o4 + 1] = __nv_bfloat162(l[2], l[3]);
    }
}

// ---------------- launch ----------------
extern "C" void kernel_launch(void* const* d_in, const int* in_sizes, int n_in,
                              void* d_out, int out_size) {
    const float* x  = (const float*)d_in[0];
    const void*  ei = d_in[1];
    const float* W1 = (const float*)d_in[2];
    const float* b1 = (const float*)d_in[3];
    const float* Wr = (const float*)d_in[4];
    const float* br = (const float*)d_in[5];
    const float* Wx = (const float*)d_in[6];
    const float* bx = (const float*)d_in[7];
    float* out      = (float*)d_out;

    const int GSMEM = 2 * (2 * BM * AST + 2 * BN * AST) * (int)sizeof(bf16);  // 61440
    cudaFuncSetAttribute(k_gemm_bf16, cudaFuncAttributeMaxDynamicSharedMemorySize, GSMEM);

    // graph prep
    k_detect<<<1, 256>>>(ei);
    k_zero_counts<<<(N_NODES + 255) / 256, 256>>>();
    k_count<<<(N_EDGES + 255) / 256, 256>>>(ei);
    k_dinv<<<(N_NODES + 255) / 256, 256>>>();
    k_scan<<<1, 1024>>>();
    k_scatter<<<(N_EDGES + 255) / 256, 256>>>(ei);

    // operand pre-split
    k_split_w<<<(C_IN * C_H1 + 255) / 256, 256>>>(W1, C_IN, C_H1, 0);
    k_split_w<<<(C_H1 * C_H1 + 255) / 256, 256>>>(Wr, C_H1, C_H1, 1);
    k_split_w<<<(C_H1 * C_OUT + 255) / 256, 256>>>(Wx, C_H1, C_OUT, 2);
    k_split_x<<<((N_NODES * C_IN / 4) + 255) / 256, 256>>>(x);

    dim3 g512(C_H1 / BN, (N_NODES + BM - 1) / BM);
    dim3 g256(C_OUT / BN, (N_NODES + BM - 1) / BM);
    const int SPB = (N_NODES + 7) / 8;    // 6250 blocks, 8 nodes each

    // layer 0: H = relu(agg(x @ W1) + b1)
    k_gemm_bf16<<<g512, 128, GSMEM>>>(0, N_NODES, C_H1, C_IN);
    for (int c = 0; c < C_H1 / 128; c++)
        k_spmm_ch<C_H1, true, false, false><<<SPB, 256>>>(b1, out, c);

    // 4 residual layers
    for (int l = 0; l < 4; l++) {
        k_gemm_bf16<<<g512, 128, GSMEM>>>(1, N_NODES, C_H1, C_H1);
        for (int c = 0; c < C_H1 / 128; c++)
            k_spmm_ch<C_H1, true, true, false><<<SPB, 256>>>(br, out, c);
    }

    // final: out = agg(H @ Wx) + bx
    k_gemm_bf16<<<g256, 128, GSMEM>>>(2, N_NODES, C_OUT, C_H1);
    for (int c = 0; c < C_OUT / 128; c++)
        k_spmm_ch<C_OUT, false, false, true><<<SPB, 256>>>(bx, out, c);
}

// round 13
// speedup vs baseline: 1.1318x; 1.0348x over previous
#include <cuda_runtime.h>
#include <cuda_bf16.h>

#define N_NODES 50000
#define N_EDGES 800000
#define C_IN   512
#define C_H1   512
#define C_OUT  256

typedef __nv_bfloat16 bf16;

// ---------------- device scratch (no allocations allowed) ----------------
__device__ __align__(16) float g_T[(size_t)N_NODES * C_H1];   // GEMM output
__device__ __align__(16) bf16  g_Hh[(size_t)N_NODES * C_H1];  // hidden hi (GEMM A)
__device__ __align__(16) bf16  g_Hl[(size_t)N_NODES * C_H1];  // hidden lo
__device__ __align__(16) bf16  g_W1h[C_IN * C_H1],  g_W1l[C_IN * C_H1];   // [N][K] transposed
__device__ __align__(16) bf16  g_Wrh[C_H1 * C_H1],  g_Wrl[C_H1 * C_H1];
__device__ __align__(16) bf16  g_Wxh[C_H1 * C_OUT], g_Wxl[C_H1 * C_OUT];
__device__ float g_dinv[N_NODES];
__device__ int   g_cnt[N_NODES];
__device__ int   g_cnt2[N_NODES];
__device__ int   g_rowptr[N_NODES + 1];
__device__ int   g_colsrc[N_EDGES];
__device__ float g_norm[N_EDGES];
__device__ int   g_is64;

__device__ __forceinline__ int edge_at(const void* ei, long long idx) {
    if (g_is64) return (int)((const long long*)ei)[idx];
    return ((const int*)ei)[idx];
}

__device__ __forceinline__ void split_bf16(float v, bf16& hi, bf16& lo) {
    hi = __float2bfloat16(v);
    lo = __float2bfloat16(v - __bfloat162float(hi));
}

// ---------------- dtype sniffer (parallel) ----------------
__global__ void k_detect(const void* ei) {
    const int* w = (const int*)ei;
    __shared__ unsigned s[256];
    unsigned acc = 0;
    for (int i = threadIdx.x; i < 2048; i += 256) acc |= (unsigned)w[2 * i + 1];
    s[threadIdx.x] = acc;
    __syncthreads();
    for (int off = 128; off > 0; off >>= 1) {
        if (threadIdx.x < off) s[threadIdx.x] |= s[threadIdx.x + off];
        __syncthreads();
    }
    if (threadIdx.x == 0) g_is64 = (s[0] == 0) ? 1 : 0;
}

// ---------------- graph prep ----------------
__global__ void k_zero_counts() {
    int i = blockIdx.x * blockDim.x + threadIdx.x;
    if (i < N_NODES) { g_cnt[i] = 0; g_cnt2[i] = 0; }
}

__global__ void k_count(const void* __restrict__ ei) {
    int e = blockIdx.x * blockDim.x + threadIdx.x;
    if (e < N_EDGES) {
        int d = edge_at(ei, (long long)N_EDGES + e);
        if (d >= 0 && d < N_NODES) atomicAdd(&g_cnt[d], 1);
    }
}

__global__ void k_dinv() {
    int i = blockIdx.x * blockDim.x + threadIdx.x;
    if (i < N_NODES) g_dinv[i] = rsqrtf((float)g_cnt[i] + 1.0f);
}

__global__ void k_scan() {
    const int T = 1024;
    int tid = threadIdx.x;
    const int chunk = (N_NODES + T - 1) / T;
    int beg = tid * chunk;
    int end = min(beg + chunk, N_NODES);
    int sum = 0;
    for (int i = beg; i < end; i++) sum += g_cnt[i];
    __shared__ int s[T];
    s[tid] = sum;
    __syncthreads();
    for (int off = 1; off < T; off <<= 1) {
        int v = (tid >= off) ? s[tid - off] : 0;
        __syncthreads();
        s[tid] += v;
        __syncthreads();
    }
    int run = (tid > 0) ? s[tid - 1] : 0;
    for (int i = beg; i < end; i++) { g_rowptr[i] = run; run += g_cnt[i]; }
    if (tid == T - 1) g_rowptr[N_NODES] = N_EDGES;
}

__global__ void k_scatter(const void* __restrict__ ei) {
    int e = blockIdx.x * blockDim.x + threadIdx.x;
    if (e < N_EDGES) {
        int s = edge_at(ei, e);
        int d = edge_at(ei, (long long)N_EDGES + e);
        if (s < 0 || s >= N_NODES || d < 0 || d >= N_NODES) return;
        int pos = g_rowptr[d] + atomicAdd(&g_cnt2[d], 1);
        if (pos >= 0 && pos < N_EDGES) {
            g_colsrc[pos] = s;
            g_norm[pos] = g_dinv[s] * g_dinv[d];
        }
    }
}

// ---------------- operand pre-split ----------------
__global__ void k_split_x(const float* __restrict__ x) {
    size_t i = (size_t)blockIdx.x * blockDim.x + threadIdx.x;
    const size_t total4 = (size_t)N_NODES * C_IN / 4;
    if (i >= total4) return;
    float4 v = ((const float4*)x)[i];
    bf16 h[4], l[4];
    split_bf16(v.x, h[0], l[0]); split_bf16(v.y, h[1], l[1]);
    split_bf16(v.z, h[2], l[2]); split_bf16(v.w, h[3], l[3]);
    ((__nv_bfloat162*)g_Hh)[2 * i]     = __nv_bfloat162(h[0], h[1]);
    ((__nv_bfloat162*)g_Hh)[2 * i + 1] = __nv_bfloat162(h[2], h[3]);
    ((__nv_bfloat162*)g_Hl)[2 * i]     = __nv_bfloat162(l[0], l[1]);
    ((__nv_bfloat162*)g_Hl)[2 * i + 1] = __nv_bfloat162(l[2], l[3]);
}

// W[K][N] fp32 -> Wt_h/Wt_l [N][K] bf16 (transposed)
__global__ void k_split_w(const float* __restrict__ W, int K, int N, int sel) {
    bf16 *Wh, *Wl;
    if (sel == 0)      { Wh = g_W1h; Wl = g_W1l; }
    else if (sel == 1) { Wh = g_Wrh; Wl = g_Wrl; }
    else               { Wh = g_Wxh; Wl = g_Wxl; }
    int idx = blockIdx.x * blockDim.x + threadIdx.x;
    if (idx >= K * N) return;
    int n = idx / K, k = idx % K;
    bf16 h, l;
    split_bf16(W[(size_t)k * N + n], h, l);
    Wh[(size_t)n * K + k] = h;
    Wl[(size_t)n * K + k] = l;
}

// ---------------- tensor-core GEMM ----------------
// 4 warps x (32x64), BM=128 BN=64 BK=32, XOR-swizzled smem (48KB -> 4 CTAs/SM),
// ldmatrix fragments, cp.async double buffer. bf16x3.
#define BM 128
#define BN 64
#define BK 32
// swizzle: row r holds 4x16B chunks; phys chunk = c ^ ((r>>1)&3)

__device__ __forceinline__ void mma_bf16(float* c, const unsigned* a, const unsigned* b) {
    asm volatile(
        "mma.sync.aligned.m16n8k16.row.col.f32.bf16.bf16.f32 "
        "{%0,%1,%2,%3}, {%4,%5,%6,%7}, {%8,%9}, {%0,%1,%2,%3};"
        : "+f"(c[0]), "+f"(c[1]), "+f"(c[2]), "+f"(c[3])
        : "r"(a[0]), "r"(a[1]), "r"(a[2]), "r"(a[3]), "r"(b[0]), "r"(b[1]));
}

__device__ __forceinline__ void ldsm4(unsigned* r, unsigned addr) {
    asm volatile("ldmatrix.sync.aligned.m8n8.x4.shared.b16 {%0,%1,%2,%3}, [%4];"
                 : "=r"(r[0]), "=r"(r[1]), "=r"(r[2]), "=r"(r[3]) : "r"(addr));
}

__device__ __forceinline__ void cp16(void* dst, const void* src, bool valid) {
    unsigned d = (unsigned)__cvta_generic_to_shared(dst);
    int sz = valid ? 16 : 0;
    asm volatile("cp.async.ca.shared.global [%0], [%1], 16, %2;\n"
                 :: "r"(d), "l"(src), "r"(sz));
}
__device__ __forceinline__ void cp_commit() { asm volatile("cp.async.commit_group;"); }
template <int NG>
__device__ __forceinline__ void cp_wait() { asm volatile("cp.async.wait_group %0;" :: "n"(NG)); }

__global__ void __launch_bounds__(128, 4)
k_gemm_bf16(int wsel, int M, int N, int K) {
    const bf16* Ah = g_Hh;
    const bf16* Al = g_Hl;
    const bf16 *Bh, *Bl;
    if (wsel == 0)      { Bh = g_W1h; Bl = g_W1l; }
    else if (wsel == 1) { Bh = g_Wrh; Bl = g_Wrl; }
    else                { Bh = g_Wxh; Bl = g_Wxl; }
    float* C = g_T;

    extern __shared__ char smem[];
    bf16* sAh = (bf16*)smem;                 // [2][BM][BK] swizzled
    bf16* sAl = sAh + 2 * BM * BK;
    bf16* sBh = sAl + 2 * BM * BK;           // [2][BN][BK] swizzled
    bf16* sBl = sBh + 2 * BN * BK;

    int tid  = threadIdx.x;
    int w    = tid >> 5;
    int lane = tid & 31;

    int row0 = blockIdx.y * BM;
    int col0 = blockIdx.x * BN;
    int wrow = w * 32;

    int a_r = (lane & 7) + ((lane >> 3) & 1) * 8;   // 0..15
    int a_c = (lane >> 4) * 8;                       // {0,8}
    int b_r = (lane & 7) + (lane >> 4) * 8;          // 0..15
    int b_c = ((lane >> 3) & 1) * 8;                 // {0,8}
    int asw = (a_r >> 1) & 3;                        // swizzle selector (row-invariant mod 16)
    int bsw = (b_r >> 1) & 3;

    unsigned uAh = (unsigned)__cvta_generic_to_shared(sAh);
    unsigned uAl = (unsigned)__cvta_generic_to_shared(sAl);
    unsigned uBh = (unsigned)__cvta_generic_to_shared(sBh);
    unsigned uBl = (unsigned)__cvta_generic_to_shared(sBl);

    float acc[2][8][4];
#pragma unroll
    for (int mg = 0; mg < 2; mg++)
#pragma unroll
        for (int n = 0; n < 8; n++)
#pragma unroll
            for (int j = 0; j < 4; j++) acc[mg][n][j] = 0.0f;

    auto prefetch = [&](int st, int kt) {
#pragma unroll
        for (int it = 0; it < 4; it++) {
            int idx = tid + it * 128;
            int r = idx >> 2, c16 = idx & 3;
            bool v = (row0 + r) < M;
            size_t goff = (size_t)(row0 + r) * K + kt + c16 * 8;
            int soff = st * BM * BK + r * BK + ((c16 ^ ((r >> 1) & 3)) << 3);
            cp16(&sAh[soff], Ah + goff, v);
            cp16(&sAl[soff], Al + goff, v);
        }
#pragma unroll
        for (int it = 0; it < 2; it++) {
            int idx = tid + it * 128;
            int r = idx >> 2, c16 = idx & 3;
            size_t goff = (size_t)(col0 + r) * K + kt + c16 * 8;
            int soff = st * BN * BK + r * BK + ((c16 ^ ((r >> 1) & 3)) << 3);
            cp16(&sBh[soff], Bh + goff, true);
            cp16(&sBl[soff], Bl + goff, true);
        }
    };

    const int nk = K / BK;
    prefetch(0, 0);
    cp_commit();

    for (int ik = 0; ik < nk; ik++) {
        int cur = ik & 1;
        if (ik + 1 < nk) {
            prefetch(cur ^ 1, (ik + 1) * BK);
            cp_commit();
            cp_wait<1>();
        } else {
            cp_wait<0>();
        }
        __syncthreads();

        int aBase = cur * BM * BK;
        int bBase = cur * BN * BK;

#pragma unroll
        for (int ks = 0; ks < BK; ks += 16) {
            unsigned ah[2][4], al[2][4];
#pragma unroll
            for (int mg = 0; mg < 2; mg++) {
                int chunk = ((ks + a_c) >> 3) ^ asw;
                int off = aBase + (wrow + mg * 16 + a_r) * BK + (chunk << 3);
                ldsm4(ah[mg], uAh + off * 2);
                ldsm4(al[mg], uAl + off * 2);
            }
#pragma unroll
            for (int p = 0; p < 4; p++) {
                unsigned bh[4], bl[4];
                int chunk = ((ks + b_c) >> 3) ^ bsw;
                int off = bBase + (16 * p + b_r) * BK + (chunk << 3);
                ldsm4(bh, uBh + off * 2);
                ldsm4(bl, uBl + off * 2);
#pragma unroll
                for (int mg = 0; mg < 2; mg++) {
                    mma_bf16(acc[mg][2 * p],     ah[mg], bh);
                    mma_bf16(acc[mg][2 * p],     ah[mg], bl);
                    mma_bf16(acc[mg][2 * p],     al[mg], bh);
                    mma_bf16(acc[mg][2 * p + 1], ah[mg], bh + 2);
                    mma_bf16(acc[mg][2 * p + 1], ah[mg], bl + 2);
                    mma_bf16(acc[mg][2 * p + 1], al[mg], bh + 2);
                }
            }
        }
        __syncthreads();
    }

#pragma unroll
    for (int mg = 0; mg < 2; mg++) {
        int r0 = row0 + wrow + mg * 16 + (lane >> 2);
#pragma unroll
        for (int n = 0; n < 8; n++) {
            int col = col0 + n * 8 + 2 * (lane & 3);
            if (r0 < M)
                *(float2*)&C[(size_t)r0 * N + col] = make_float2(acc[mg][n][0], acc[mg][n][1]);
            if (r0 + 8 < M)
                *(float2*)&C[(size_t)(r0 + 8) * N + col] = make_float2(acc[mg][n][2], acc[mg][n][3]);
        }
    }
}

// ---------------- channel-chunked CSR SpMM with fused epilogue ----------------
template <int CHT, bool RELU, bool RES, bool TO_OUT>
__global__ void __launch_bounds__(256)
k_spmm_ch(const float* __restrict__ bias, float* __restrict__ out, int chunk) {
    constexpr int V4T = CHT / 4;
    int slot = threadIdx.x >> 5;
    int lane = threadIdx.x & 31;
    int i = blockIdx.x * 8 + slot;
    if (i >= N_NODES) return;
    int c4 = chunk * 32 + lane;

    const float4* T4 = (const float4*)g_T;

    float di = g_dinv[i];
    float wself = di * di;
    float4 tv = T4[(size_t)i * V4T + c4];
    float4 acc = make_float4(tv.x * wself, tv.y * wself, tv.z * wself, tv.w * wself);

    int e = g_rowptr[i];
    int end = g_rowptr[i + 1];
    for (; e + 4 <= end; e += 4) {
        int   s0 = g_colsrc[e],     s1 = g_colsrc[e + 1];
        int   s2 = g_colsrc[e + 2], s3 = g_colsrc[e + 3];
        float w0 = g_norm[e],       w1 = g_norm[e + 1];
        float w2 = g_norm[e + 2],   w3 = g_norm[e + 3];
        float4 v0 = T4[(size_t)s0 * V4T + c4];
        float4 v1 = T4[(size_t)s1 * V4T + c4];
        float4 v2 = T4[(size_t)s2 * V4T + c4];
        float4 v3 = T4[(size_t)s3 * V4T + c4];
        acc.x += w0 * v0.x + w1 * v1.x + w2 * v2.x + w3 * v3.x;
        acc.y += w0 * v0.y + w1 * v1.y + w2 * v2.y + w3 * v3.y;
        acc.z += w0 * v0.z + w1 * v1.z + w2 * v2.z + w3 * v3.z;
        acc.w += w0 * v0.w + w1 * v1.w + w2 * v2.w + w3 * v3.w;
    }
    for (; e < end; e++) {
        int s = g_colsrc[e];
        float wgt = g_norm[e];
        float4 v = T4[(size_t)s * V4T + c4];
        acc.x += wgt * v.x; acc.y += wgt * v.y; acc.z += wgt * v.z; acc.w += wgt * v.w;
    }

    float4 b = ((const float4*)bias)[c4];
    acc.x += b.x; acc.y += b.y; acc.z += b.z; acc.w += b.w;

    if (RELU) {
        acc.x = fmaxf(acc.x, 0.f); acc.y = fmaxf(acc.y, 0.f);
        acc.z = fmaxf(acc.z, 0.f); acc.w = fmaxf(acc.w, 0.f);
    }

    size_t o4 = (size_t)i * V4T + c4;

    if (RES) {
        __nv_bfloat162 h0 = ((const __nv_bfloat162*)g_Hh)[2 * o4];
        __nv_bfloat162 h1 = ((const __nv_bfloat162*)g_Hh)[2 * o4 + 1];
        __nv_bfloat162 l0 = ((const __nv_bfloat162*)g_Hl)[2 * o4];
        __nv_bfloat162 l1 = ((const __nv_bfloat162*)g_Hl)[2 * o4 + 1];
        acc.x += __bfloat162float(h0.x) + __bfloat162float(l0.x);
        acc.y += __bfloat162float(h0.y) + __bfloat162float(l0.y);
        acc.z += __bfloat162float(h1.x) + __bfloat162float(l1.x);
        acc.w += __bfloat162float(h1.y) + __bfloat162float(l1.y);
    }

    if (TO_OUT) {
        ((float4*)out)[o4] = acc;
    } else {
        bf16 h[4], l[4];
        split_bf16(acc.x, h[0], l[0]); split_bf16(acc.y, h[1], l[1]);
        split_bf16(acc.z, h[2], l[2]); split_bf16(acc.w, h[3], l[3]);
        ((__nv_bfloat162*)g_Hh)[2 * o4]     = __nv_bfloat162(h[0], h[1]);
        ((__nv_bfloat162*)g_Hh)[2 * o4 + 1] = __nv_bfloat162(h[2], h[3]);
        ((__nv_bfloat162*)g_Hl)[2 * o4]     = __nv_bfloat162(l[0], l[1]);
        ((__nv_bfloat162*)g_Hl)[2 * o4 + 1] = __nv_bfloat162(l[2], l[3]);
    }
}

// ---------------- launch ----------------
extern "C" void kernel_launch(void* const* d_in, const int* in_sizes, int n_in,
                              void* d_out, int out_size) {
    const float* x  = (const float*)d_in[0];
    const void*  ei = d_in[1];
    const float* W1 = (const float*)d_in[2];
    const float* b1 = (const float*)d_in[3];
    const float* Wr = (const float*)d_in[4];
    const float* br = (const float*)d_in[5];
    const float* Wx = (const float*)d_in[6];
    const float* bx = (const float*)d_in[7];
    float* out      = (float*)d_out;

    const int GSMEM = 2 * (2 * BM * BK + 2 * BN * BK) * (int)sizeof(bf16);  // 49152
    cudaFuncSetAttribute(k_gemm_bf16, cudaFuncAttributeMaxDynamicSharedMemorySize, GSMEM);

    dim3 g512(C_H1 / BN, (N_NODES + BM - 1) / BM);
    dim3 g256(C_OUT / BN, (N_NODES + BM - 1) / BM);
    const int SPB = (N_NODES + 7) / 8;

    // splits first (only depend on inputs), so the first GEMM lands in the
    // ncu-profiled launch slot and we finally get GEMM metrics.
    k_split_x<<<((N_NODES * C_IN / 4) + 255) / 256, 256>>>(x);
    k_split_w<<<(C_IN * C_H1 + 255) / 256, 256>>>(W1, C_IN, C_H1, 0);
    k_split_w<<<(C_H1 * C_H1 + 255) / 256, 256>>>(Wr, C_H1, C_H1, 1);

    // layer-0 GEMM (launch #4)
    k_gemm_bf16<<<g512, 128, GSMEM>>>(0, N_NODES, C_H1, C_IN);

    k_split_w<<<(C_H1 * C_OUT + 255) / 256, 256>>>(Wx, C_H1, C_OUT, 2);

    // graph prep (must finish before the first SpMM)
    k_detect<<<1, 256>>>(ei);
    k_zero_counts<<<(N_NODES + 255) / 256, 256>>>();
    k_count<<<(N_EDGES + 255) / 256, 256>>>(ei);
    k_dinv<<<(N_NODES + 255) / 256, 256>>>();
    k_scan<<<1, 1024>>>();
    k_scatter<<<(N_EDGES + 255) / 256, 256>>>(ei);

    // layer 0 aggregate: H = relu(agg(x @ W1) + b1)
    for (int c = 0; c < C_H1 / 128; c++)
        k_spmm_ch<C_H1, true, false, false><<<SPB, 256>>>(b1, out, c);

    // 4 residual layers
    for (int l = 0; l < 4; l++) {
        k_gemm_bf16<<<g512, 128, GSMEM>>>(1, N_NODES, C_H1, C_H1);
        for (int c = 0; c < C_H1 / 128; c++)
            k_spmm_ch<C_H1, true, true, false><<<SPB, 256>>>(br, out, c);
    }

    // final: out = agg(H @ Wx) + bx
    k_gemm_bf16<<<g256, 128, GSMEM>>>(2, N_NODES, C_OUT, C_H1);
    for (int c = 0; c < C_OUT / 128; c++)
        k_spmm_ch<C_OUT, false, false, true><<<SPB, 256>>>(bx, out, c);
}